// round 1
// baseline (speedup 1.0000x reference)
#include <cuda_runtime.h>

// Problem dims (fixed by the dataset)
#define Bc  4
#define Sc  2048
#define Ec  1024
#define Hc  16
#define Dc  64
#define HDc (Hc * Dc)      // 1024
#define Mc  (Bc * Sc)      // 8192

// Scratch: Q,K,V in [B,H,S,D]; AO (concat heads) in [B,S,H*D]
__device__ float g_Q[Bc * Hc * Sc * Dc];
__device__ float g_K[Bc * Hc * Sc * Dc];
__device__ float g_V[Bc * Hc * Sc * Dc];
__device__ float g_AO[Bc * Sc * HDc];

// ---------------------------------------------------------------------------
// Kernel 1: fused QKV projection.
// GEMM: X[8192,1024] x W[1024, 64] per head (+bias), output scattered to
// [B,H,S,D]. blockIdx.z selects q/k/v. Tiles: BM=128, BN=64(=one head), BK=16.
// 256 threads, 8x4 register blocking.
// ---------------------------------------------------------------------------
__global__ __launch_bounds__(256) void qkv_gemm_kernel(
    const float* __restrict__ x,
    const float* __restrict__ Wq, const float* __restrict__ bq,
    const float* __restrict__ Wk, const float* __restrict__ bk,
    const float* __restrict__ Wv, const float* __restrict__ bv)
{
    constexpr int BM = 128, BN = 64, BK = 16;
    __shared__ float As[BK][BM];
    __shared__ float Bs[BK][BN];

    const int mat = blockIdx.z;
    const float* __restrict__ W    = (mat == 0) ? Wq : ((mat == 1) ? Wk : Wv);
    const float* __restrict__ bias = (mat == 0) ? bq : ((mat == 1) ? bk : bv);
    float* __restrict__ Out        = (mat == 0) ? g_Q : ((mat == 1) ? g_K : g_V);

    const int tid = threadIdx.x;
    const int tx = tid & 15;         // 0..15 -> 64 N cols (x4)
    const int ty = tid >> 4;         // 0..15 -> 128 M rows (x8)
    const int m0 = blockIdx.y * BM;
    const int n0 = blockIdx.x * BN;
    const int h  = n0 / Dc;          // BN == Dc: tile = one head

    float acc[8][4];
#pragma unroll
    for (int i = 0; i < 8; i++)
#pragma unroll
        for (int j = 0; j < 4; j++) acc[i][j] = 0.0f;

    for (int k0 = 0; k0 < Ec; k0 += BK) {
        // A tile: 128x16 = 512 float4 loads, 2 per thread (store transposed)
#pragma unroll
        for (int it = 0; it < 2; it++) {
            int i  = tid + it * 256;      // 0..511
            int m  = i >> 2;
            int kq = (i & 3) * 4;
            float4 v = *(const float4*)(x + (size_t)(m0 + m) * Ec + k0 + kq);
            As[kq + 0][m] = v.x;
            As[kq + 1][m] = v.y;
            As[kq + 2][m] = v.z;
            As[kq + 3][m] = v.w;
        }
        // B tile: 16x64 = 256 float4 loads, 1 per thread
        {
            int k  = tid >> 4;
            int dq = (tid & 15) * 4;
            float4 v = *(const float4*)(W + ((size_t)h * Ec + k0 + k) * Dc + dq);
            *(float4*)&Bs[k][dq] = v;
        }
        __syncthreads();

#pragma unroll
        for (int kk = 0; kk < BK; kk++) {
            float4 a0 = *(float4*)&As[kk][ty * 8];
            float4 a1 = *(float4*)&As[kk][ty * 8 + 4];
            float4 b4 = *(float4*)&Bs[kk][tx * 4];
            float a[8] = {a0.x, a0.y, a0.z, a0.w, a1.x, a1.y, a1.z, a1.w};
            float b[4] = {b4.x, b4.y, b4.z, b4.w};
#pragma unroll
            for (int i = 0; i < 8; i++)
#pragma unroll
                for (int j = 0; j < 4; j++)
                    acc[i][j] += a[i] * b[j];
        }
        __syncthreads();
    }

    // Epilogue: scatter to [B,H,S,D] (+bias)
#pragma unroll
    for (int i = 0; i < 8; i++) {
        int m  = m0 + ty * 8 + i;
        int bI = m / Sc;
        int s  = m % Sc;
        float* orow = Out + (((size_t)bI * Hc + h) * Sc + s) * Dc;
#pragma unroll
        for (int j = 0; j < 4; j++) {
            int d = tx * 4 + j;
            orow[d] = acc[i][j] + bias[h * Dc + d];
        }
    }
}

// ---------------------------------------------------------------------------
// Kernel 2: flash attention (causal, online softmax), fp32.
// Block = one (b,h) x one 64-row Q tile. K/V tiles of 32 rows.
// 256 threads: thread t -> q-row t/4, d-slice (t%4)*16..+16, k-cols strided
// (t%4 + 4j) so smem banks don't alias. Per-row softmax state replicated
// across the 4 threads of a row (same warp; shfl_xor 1,2).
// ---------------------------------------------------------------------------
__global__ __launch_bounds__(256) void flash_attn_kernel()
{
    constexpr int BQ = 64, BKT = 32;
    __shared__ float Qs[BQ][Dc + 4];    // pad 4: conflict-free row access
    __shared__ float Ks[BKT][Dc + 4];
    __shared__ float Vs[BKT][Dc + 4];
    __shared__ float Ps[BQ][BKT + 1];   // pad 1: conflict-free column access

    const int bh = blockIdx.y;          // b*H + h
    const int b  = bh / Hc;
    const int h  = bh % Hc;
    const int q0 = blockIdx.x * BQ;

    const float* __restrict__ Qb = g_Q + (size_t)bh * Sc * Dc;
    const float* __restrict__ Kb = g_K + (size_t)bh * Sc * Dc;
    const float* __restrict__ Vb = g_V + (size_t)bh * Sc * Dc;

    const int tid = threadIdx.x;
    const int qr  = tid >> 2;           // 0..63
    const int sub = tid & 3;            // 0..3
    const int qg  = q0 + qr;            // global query row

    // Load Q tile: 64x64 = 1024 float4, 4 per thread
#pragma unroll
    for (int it = 0; it < 4; it++) {
        int i  = tid + it * 256;
        int r  = i >> 4;
        int c4 = (i & 15) * 4;
        *(float4*)&Qs[r][c4] = *(const float4*)(Qb + (size_t)(q0 + r) * Dc + c4);
    }

    float acc[16];
#pragma unroll
    for (int i = 0; i < 16; i++) acc[i] = 0.0f;
    float mrow = -1e30f, lrow = 0.0f;

    const int kend = q0 + BQ;           // causal: k < q0+64
    for (int k0 = 0; k0 < kend; k0 += BKT) {
        __syncthreads();                // prev PV done before K/V overwrite
        // Load K,V tiles: 32x64 = 512 float4 each, 2 per thread each
#pragma unroll
        for (int it = 0; it < 2; it++) {
            int i  = tid + it * 256;
            int r  = i >> 4;
            int c4 = (i & 15) * 4;
            *(float4*)&Ks[r][c4] = *(const float4*)(Kb + (size_t)(k0 + r) * Dc + c4);
            *(float4*)&Vs[r][c4] = *(const float4*)(Vb + (size_t)(k0 + r) * Dc + c4);
        }
        __syncthreads();

        // Scores: 8 strided k-cols per thread, jj = sub + 4*j
        float s[8];
#pragma unroll
        for (int j = 0; j < 8; j++) s[j] = 0.0f;
#pragma unroll
        for (int d4 = 0; d4 < 16; d4++) {
            float4 qv = *(float4*)&Qs[qr][d4 * 4];
#pragma unroll
            for (int j = 0; j < 8; j++) {
                int jj = sub + j * 4;
                float4 kv = *(float4*)&Ks[jj][d4 * 4];
                s[j] += qv.x * kv.x + qv.y * kv.y + qv.z * kv.z + qv.w * kv.w;
            }
        }
        float mx = -1e30f;
#pragma unroll
        for (int j = 0; j < 8; j++) {
            int kg = k0 + sub + j * 4;
            s[j] = (kg <= qg) ? s[j] * 0.125f : -1e30f;   // 1/sqrt(64)
            mx = fmaxf(mx, s[j]);
        }
        // row max across the 4 threads of this row (same warp)
        mx = fmaxf(mx, __shfl_xor_sync(0xffffffffu, mx, 1));
        mx = fmaxf(mx, __shfl_xor_sync(0xffffffffu, mx, 2));
        float mnew  = fmaxf(mrow, mx);
        float alpha = __expf(mrow - mnew);

        float psum = 0.0f;
#pragma unroll
        for (int j = 0; j < 8; j++) {
            float p = __expf(s[j] - mnew);
            Ps[qr][sub + j * 4] = p;
            psum += p;
        }
        psum += __shfl_xor_sync(0xffffffffu, psum, 1);
        psum += __shfl_xor_sync(0xffffffffu, psum, 2);
        lrow = lrow * alpha + psum;
        mrow = mnew;
#pragma unroll
        for (int i = 0; i < 16; i++) acc[i] *= alpha;

        __syncwarp();   // Ps row written by 4 same-warp threads

        // PV: acc[d-slice] += sum_j P[qr][j] * V[j][d-slice]
        const int dbase = sub * 16;
#pragma unroll
        for (int j = 0; j < BKT; j++) {
            float p = Ps[qr][j];
            float4 v0 = *(float4*)&Vs[j][dbase];
            float4 v1 = *(float4*)&Vs[j][dbase + 4];
            float4 v2 = *(float4*)&Vs[j][dbase + 8];
            float4 v3 = *(float4*)&Vs[j][dbase + 12];
            acc[0]  += p * v0.x;  acc[1]  += p * v0.y;
            acc[2]  += p * v0.z;  acc[3]  += p * v0.w;
            acc[4]  += p * v1.x;  acc[5]  += p * v1.y;
            acc[6]  += p * v1.z;  acc[7]  += p * v1.w;
            acc[8]  += p * v2.x;  acc[9]  += p * v2.y;
            acc[10] += p * v2.z;  acc[11] += p * v2.w;
            acc[12] += p * v3.x;  acc[13] += p * v3.y;
            acc[14] += p * v3.z;  acc[15] += p * v3.w;
        }
    }

    // Write to AO in [B, S, H*D] layout
    float inv_l = 1.0f / lrow;
    float* orow = g_AO + ((size_t)b * Sc + qg) * HDc + h * Dc + sub * 16;
#pragma unroll
    for (int i = 0; i < 16; i++) orow[i] = acc[i] * inv_l;
}

// ---------------------------------------------------------------------------
// Kernel 3: output projection. AO[8192,1024] x Wo[1024,1024] + bo.
// Same tiling as kernel 1 (BM=128, BN=64, BK=16).
// ---------------------------------------------------------------------------
__global__ __launch_bounds__(256) void out_gemm_kernel(
    const float* __restrict__ Wo, const float* __restrict__ bo,
    float* __restrict__ out)
{
    constexpr int BM = 128, BN = 64, BK = 16;
    __shared__ float As[BK][BM];
    __shared__ float Bs[BK][BN];

    const int tid = threadIdx.x;
    const int tx = tid & 15;
    const int ty = tid >> 4;
    const int m0 = blockIdx.y * BM;
    const int n0 = blockIdx.x * BN;

    float acc[8][4];
#pragma unroll
    for (int i = 0; i < 8; i++)
#pragma unroll
        for (int j = 0; j < 4; j++) acc[i][j] = 0.0f;

    for (int k0 = 0; k0 < HDc; k0 += BK) {
#pragma unroll
        for (int it = 0; it < 2; it++) {
            int i  = tid + it * 256;
            int m  = i >> 2;
            int kq = (i & 3) * 4;
            float4 v = *(const float4*)(g_AO + (size_t)(m0 + m) * HDc + k0 + kq);
            As[kq + 0][m] = v.x;
            As[kq + 1][m] = v.y;
            As[kq + 2][m] = v.z;
            As[kq + 3][m] = v.w;
        }
        {
            int k  = tid >> 4;
            int dq = (tid & 15) * 4;
            float4 v = *(const float4*)(Wo + (size_t)(k0 + k) * Ec + n0 + dq);
            *(float4*)&Bs[k][dq] = v;
        }
        __syncthreads();

#pragma unroll
        for (int kk = 0; kk < BK; kk++) {
            float4 a0 = *(float4*)&As[kk][ty * 8];
            float4 a1 = *(float4*)&As[kk][ty * 8 + 4];
            float4 b4 = *(float4*)&Bs[kk][tx * 4];
            float a[8] = {a0.x, a0.y, a0.z, a0.w, a1.x, a1.y, a1.z, a1.w};
            float b[4] = {b4.x, b4.y, b4.z, b4.w};
#pragma unroll
            for (int i = 0; i < 8; i++)
#pragma unroll
                for (int j = 0; j < 4; j++)
                    acc[i][j] += a[i] * b[j];
        }
        __syncthreads();
    }

#pragma unroll
    for (int i = 0; i < 8; i++) {
        int m = m0 + ty * 8 + i;
        float* orow = out + (size_t)m * Ec + n0;
#pragma unroll
        for (int j = 0; j < 4; j++) {
            int n = tx * 4 + j;
            orow[n] = acc[i][j] + bo[n0 + n];
        }
    }
}

// ---------------------------------------------------------------------------
extern "C" void kernel_launch(void* const* d_in, const int* in_sizes, int n_in,
                              void* d_out, int out_size)
{
    const float* x  = (const float*)d_in[0];
    const float* Wq = (const float*)d_in[1];
    const float* bq = (const float*)d_in[2];
    const float* Wk = (const float*)d_in[3];
    const float* bk = (const float*)d_in[4];
    const float* Wv = (const float*)d_in[5];
    const float* bv = (const float*)d_in[6];
    const float* Wo = (const float*)d_in[7];
    const float* bo = (const float*)d_in[8];
    float* out = (float*)d_out;

    dim3 g1(HDc / 64, Mc / 128, 3);
    qkv_gemm_kernel<<<g1, 256>>>(x, Wq, bq, Wk, bk, Wv, bv);

    dim3 g2(Sc / 64, Bc * Hc);
    flash_attn_kernel<<<g2, 256>>>();

    dim3 g3(Ec / 64, Mc / 128);
    out_gemm_kernel<<<g3, 256>>>(Wo, bo, out);
}

// round 4
// speedup vs baseline: 5.5812x; 5.5812x over previous
#include <cuda_runtime.h>

// Problem dims (fixed)
#define Bc  4
#define Sc  2048
#define Ec  1024
#define Hc  16
#define Dc  64
#define HDc (Hc * Dc)      // 1024
#define Mc  (Bc * Sc)      // 8192

// Scratch: Q,K,V in [B,H,S,D] (tf32-rounded fp32); AO in [B,S,H*D]
__device__ float g_Q[Bc * Hc * Sc * Dc];
__device__ float g_K[Bc * Hc * Sc * Dc];
__device__ float g_V[Bc * Hc * Sc * Dc];
__device__ float g_AO[Bc * Sc * HDc];

// ---------------------------------------------------------------------------
// helpers
// ---------------------------------------------------------------------------
__device__ __forceinline__ unsigned f2tf32(float x) {
    unsigned r;
    asm("cvt.rna.tf32.f32 %0, %1;" : "=r"(r) : "f"(x));
    return r;
}
__device__ __forceinline__ float tf32r(float x) { return __uint_as_float(f2tf32(x)); }

__device__ __forceinline__ void mma8(float* d, const unsigned* a, unsigned b0, unsigned b1) {
    asm volatile(
        "mma.sync.aligned.m16n8k8.row.col.f32.tf32.tf32.f32 "
        "{%0,%1,%2,%3}, {%4,%5,%6,%7}, {%8,%9}, {%0,%1,%2,%3};"
        : "+f"(d[0]), "+f"(d[1]), "+f"(d[2]), "+f"(d[3])
        : "r"(a[0]), "r"(a[1]), "r"(a[2]), "r"(a[3]), "r"(b0), "r"(b1));
}

__device__ __forceinline__ void cp16(void* smem, const void* g) {
    unsigned sa = (unsigned)__cvta_generic_to_shared(smem);
    asm volatile("cp.async.cg.shared.global [%0], [%1], 16;" :: "r"(sa), "l"(g));
}
#define CP_COMMIT asm volatile("cp.async.commit_group;")
#define CP_WAIT0  asm volatile("cp.async.wait_group 0;")

// ---------------------------------------------------------------------------
// tf32 GEMM, block tile 128(M) x 64(N) x 32(K), 256 thr = 8 warps (4x2),
// warp tile 32x32 = 2(m16) x 4(n8). Register-prefetch double buffering.
// MODE 0: QKV projection (A = x param, B = W[h], scatter to [B,H,S,D], tf32-round)
// MODE 1: output projection (A = g_AO bound in DEVICE code, B = Wo, fp32 out)
// ---------------------------------------------------------------------------
template <int MODE>
__global__ __launch_bounds__(256) void gemm_tf32_kernel(
    const float* __restrict__ Ap,
    const float* __restrict__ Wq, const float* __restrict__ bq,
    const float* __restrict__ Wk, const float* __restrict__ bk,
    const float* __restrict__ Wv, const float* __restrict__ bv,
    float* __restrict__ outp)
{
    __shared__ unsigned As[128][36];   // [m][k], ld 36 -> frag bank = 4r+c = lane
    __shared__ unsigned Bs[32][72];    // [k][n], ld 72 -> frag bank = 8c+g

    // g_AO must be bound in device code (host-side __device__ symbol decay is bogus)
    const float* __restrict__ A = (MODE == 0) ? Ap : (const float*)g_AO;

    const float* __restrict__ W;
    const float* __restrict__ bias;
    float* __restrict__ Out;
    int ldb, ncol0;
    if (MODE == 0) {
        const int mat = blockIdx.z;
        W    = (mat == 0) ? Wq : (mat == 1) ? Wk : Wv;
        bias = (mat == 0) ? bq : (mat == 1) ? bk : bv;
        Out  = (mat == 0) ? g_Q : (mat == 1) ? g_K : g_V;
        W   += (size_t)blockIdx.x * Ec * Dc;   // head base
        ldb  = Dc;
        ncol0 = 0;
    } else {
        W = Wq;  bias = bq;  Out = outp;
        ldb = Ec; ncol0 = blockIdx.x * 64;
    }

    const int tid  = threadIdx.x;
    const int warp = tid >> 5, lane = tid & 31;
    const int wm = warp >> 1, wn = warp & 1;
    const int r = lane >> 2, c = lane & 3;
    const int m0 = blockIdx.y * 128;

    float4 pa[4], pb[2];

    // prefetch tile 0
#pragma unroll
    for (int it = 0; it < 4; it++) {
        int i = tid + it * 256; int m = i >> 3; int kq = (i & 7) * 4;
        pa[it] = *(const float4*)(A + (size_t)(m0 + m) * 1024 + kq);
    }
#pragma unroll
    for (int it = 0; it < 2; it++) {
        int i = tid + it * 256; int kb = i >> 4; int nq = (i & 15) * 4;
        pb[it] = *(const float4*)(W + (size_t)kb * ldb + ncol0 + nq);
    }

    float acc[2][4][4];
#pragma unroll
    for (int mt = 0; mt < 2; mt++)
#pragma unroll
        for (int nt = 0; nt < 4; nt++)
#pragma unroll
            for (int j = 0; j < 4; j++) acc[mt][nt][j] = 0.0f;

    for (int k0 = 0; k0 < 1024; k0 += 32) {
        // store staged tile (convert to tf32)
#pragma unroll
        for (int it = 0; it < 4; it++) {
            int i = tid + it * 256; int m = i >> 3; int kq = (i & 7) * 4;
            *(uint4*)&As[m][kq] = make_uint4(f2tf32(pa[it].x), f2tf32(pa[it].y),
                                             f2tf32(pa[it].z), f2tf32(pa[it].w));
        }
#pragma unroll
        for (int it = 0; it < 2; it++) {
            int i = tid + it * 256; int kb = i >> 4; int nq = (i & 15) * 4;
            *(uint4*)&Bs[kb][nq] = make_uint4(f2tf32(pb[it].x), f2tf32(pb[it].y),
                                              f2tf32(pb[it].z), f2tf32(pb[it].w));
        }
        __syncthreads();

        if (k0 + 32 < 1024) {   // prefetch next tile
#pragma unroll
            for (int it = 0; it < 4; it++) {
                int i = tid + it * 256; int m = i >> 3; int kq = (i & 7) * 4;
                pa[it] = *(const float4*)(A + (size_t)(m0 + m) * 1024 + k0 + 32 + kq);
            }
#pragma unroll
            for (int it = 0; it < 2; it++) {
                int i = tid + it * 256; int kb = i >> 4; int nq = (i & 15) * 4;
                pb[it] = *(const float4*)(W + (size_t)(k0 + 32 + kb) * ldb + ncol0 + nq);
            }
        }

#pragma unroll
        for (int kk = 0; kk < 4; kk++) {
            unsigned af[2][4];
#pragma unroll
            for (int mt = 0; mt < 2; mt++) {
                int R = wm * 32 + mt * 16;
                af[mt][0] = As[R + r][kk * 8 + c];
                af[mt][1] = As[R + r + 8][kk * 8 + c];
                af[mt][2] = As[R + r][kk * 8 + c + 4];
                af[mt][3] = As[R + r + 8][kk * 8 + c + 4];
            }
#pragma unroll
            for (int nt = 0; nt < 4; nt++) {
                int Cn = wn * 32 + nt * 8;
                unsigned b0 = Bs[kk * 8 + c][Cn + r];
                unsigned b1 = Bs[kk * 8 + c + 4][Cn + r];
#pragma unroll
                for (int mt = 0; mt < 2; mt++)
                    mma8(acc[mt][nt], af[mt], b0, b1);
            }
        }
        __syncthreads();
    }

    // epilogue
    if (MODE == 0) {
        const int h = blockIdx.x;
        const float* bh = bias + h * Dc;
        int bI = m0 >> 11;
        int sBase = m0 & 2047;
#pragma unroll
        for (int mt = 0; mt < 2; mt++) {
            int lr = wm * 32 + mt * 16 + r;
#pragma unroll
            for (int nt = 0; nt < 4; nt++) {
                int d = wn * 32 + nt * 8 + 2 * c;
                float bb0 = bh[d], bb1 = bh[d + 1];
                size_t base0 = ((((size_t)bI * Hc + h) * Sc) + sBase + lr) * Dc + d;
                float2 v0 = make_float2(tf32r(acc[mt][nt][0] + bb0), tf32r(acc[mt][nt][1] + bb1));
                float2 v1 = make_float2(tf32r(acc[mt][nt][2] + bb0), tf32r(acc[mt][nt][3] + bb1));
                *(float2*)(Out + base0)            = v0;
                *(float2*)(Out + base0 + 8 * Dc)   = v1;
            }
        }
    } else {
#pragma unroll
        for (int mt = 0; mt < 2; mt++) {
            int mrow = m0 + wm * 32 + mt * 16 + r;
#pragma unroll
            for (int nt = 0; nt < 4; nt++) {
                int d = ncol0 + wn * 32 + nt * 8 + 2 * c;
                float bb0 = bias[d], bb1 = bias[d + 1];
                *(float2*)(Out + (size_t)mrow * 1024 + d) =
                    make_float2(acc[mt][nt][0] + bb0, acc[mt][nt][1] + bb1);
                *(float2*)(Out + (size_t)(mrow + 8) * 1024 + d) =
                    make_float2(acc[mt][nt][2] + bb0, acc[mt][nt][3] + bb1);
            }
        }
    }
}

// ---------------------------------------------------------------------------
// Flash attention, tf32 tensor cores. 128 thr = 4 warps; BQ=64 (16 q-rows per
// warp), BKT=64, D=64. K/V double-buffered via cp.async. Online softmax on
// C-fragment layout. Ps row stride = 68 (64 cols + pad; PV frag loads are
// bank-conflict-free: 68 % 32 == 4 -> bank = 4r + c + 8k, 4r+c == lane).
// Dynamic smem u32 layout:
//   buf0 Ks@0 (64*68=4352)  Vs@4352 (64*72=4608)
//   buf1 Ks@8960            Vs@13312
//   Ps@17920 + warp*1088 (16*68)  -> total 22272 u32 = 89088 B
// ---------------------------------------------------------------------------
#define PS_LD   68
#define PS_BASE 17920
#define SMEM_BYTES 89088

__device__ __forceinline__ void stage_kv(unsigned* Ksb, unsigned* Vsb,
                                         const float* Kb, const float* Vb,
                                         int k0, int tid)
{
#pragma unroll
    for (int it = 0; it < 8; it++) {
        int i = tid + it * 128;
        int row = i >> 4;
        int cq = (i & 15) * 4;
        cp16(&Ksb[row * 68 + cq], Kb + (size_t)(k0 + row) * Dc + cq);
        cp16(&Vsb[row * 72 + cq], Vb + (size_t)(k0 + row) * Dc + cq);
    }
}

__global__ __launch_bounds__(128) void flash_tf32_kernel()
{
    extern __shared__ __align__(16) unsigned sm[];

    const int bh = blockIdx.y;
    const int b  = bh >> 4, h = bh & 15;
    const int q0 = blockIdx.x * 64;

    const float* __restrict__ Qb = g_Q + (size_t)bh * Sc * Dc;
    const float* __restrict__ Kb = g_K + (size_t)bh * Sc * Dc;
    const float* __restrict__ Vb = g_V + (size_t)bh * Sc * Dc;

    const int tid  = threadIdx.x;
    const int warp = tid >> 5, lane = tid & 31;
    const int r = lane >> 2, c = lane & 3;

    // ---- stage Q through buf0's Ks region, extract A-fragments -------------
#pragma unroll
    for (int it = 0; it < 8; it++) {
        int i = tid + it * 128;
        int row = i >> 4, cq = (i & 15) * 4;
        *(uint4*)&sm[row * 68 + cq] = *(const uint4*)(Qb + (size_t)(q0 + row) * Dc + cq);
    }
    __syncthreads();
    unsigned qf[8][4];
    {
        int R = warp * 16;
#pragma unroll
        for (int kk = 0; kk < 8; kk++) {
            qf[kk][0] = sm[(R + r) * 68 + kk * 8 + c];
            qf[kk][1] = sm[(R + r + 8) * 68 + kk * 8 + c];
            qf[kk][2] = sm[(R + r) * 68 + kk * 8 + c + 4];
            qf[kk][3] = sm[(R + r + 8) * 68 + kk * 8 + c + 4];
        }
    }
    __syncthreads();

    unsigned* Ps = sm + PS_BASE + warp * (16 * PS_LD);

    const int nkt = blockIdx.x + 1;
    stage_kv(sm, sm + 4352, Kb, Vb, 0, tid);
    CP_COMMIT;

    float of[8][4];
#pragma unroll
    for (int nt = 0; nt < 8; nt++)
#pragma unroll
        for (int j = 0; j < 4; j++) of[nt][j] = 0.0f;
    float m_lo = -1e30f, m_hi = -1e30f, l_lo = 0.0f, l_hi = 0.0f;

    const int qlo = q0 + warp * 16 + r;
    const int qhi = qlo + 8;

    int buf = 0;
    for (int kt = 0; kt < nkt; kt++) {
        CP_WAIT0;
        __syncthreads();
        if (kt + 1 < nkt) {
            int nb = buf ^ 1;
            stage_kv(sm + nb * 8960, sm + nb * 8960 + 4352, Kb, Vb, (kt + 1) * 64, tid);
            CP_COMMIT;
        }
        unsigned* Ksb = sm + buf * 8960;
        unsigned* Vsb = Ksb + 4352;

        // ---- S = Q K^T ------------------------------------------------------
        float sf[8][4];
#pragma unroll
        for (int nt = 0; nt < 8; nt++) {
            sf[nt][0] = sf[nt][1] = sf[nt][2] = sf[nt][3] = 0.0f;
#pragma unroll
            for (int kk = 0; kk < 8; kk++) {
                unsigned b0 = Ksb[(nt * 8 + r) * 68 + kk * 8 + c];
                unsigned b1 = Ksb[(nt * 8 + r) * 68 + kk * 8 + c + 4];
                mma8(sf[nt], qf[kk], b0, b1);
            }
        }

        // ---- scale + causal mask + online softmax ---------------------------
        const int kbase = kt * 64;
        float mx_lo = -1e30f, mx_hi = -1e30f;
#pragma unroll
        for (int nt = 0; nt < 8; nt++) {
            int kg0 = kbase + nt * 8 + 2 * c;
            int kg1 = kg0 + 1;
            float s0 = sf[nt][0] * 0.125f; if (kg0 > qlo) s0 = -1e30f;
            float s1 = sf[nt][1] * 0.125f; if (kg1 > qlo) s1 = -1e30f;
            float s2 = sf[nt][2] * 0.125f; if (kg0 > qhi) s2 = -1e30f;
            float s3 = sf[nt][3] * 0.125f; if (kg1 > qhi) s3 = -1e30f;
            sf[nt][0] = s0; sf[nt][1] = s1; sf[nt][2] = s2; sf[nt][3] = s3;
            mx_lo = fmaxf(mx_lo, fmaxf(s0, s1));
            mx_hi = fmaxf(mx_hi, fmaxf(s2, s3));
        }
        mx_lo = fmaxf(mx_lo, __shfl_xor_sync(0xffffffffu, mx_lo, 1));
        mx_lo = fmaxf(mx_lo, __shfl_xor_sync(0xffffffffu, mx_lo, 2));
        mx_hi = fmaxf(mx_hi, __shfl_xor_sync(0xffffffffu, mx_hi, 1));
        mx_hi = fmaxf(mx_hi, __shfl_xor_sync(0xffffffffu, mx_hi, 2));

        float mn_lo = fmaxf(m_lo, mx_lo), mn_hi = fmaxf(m_hi, mx_hi);
        float a_lo = __expf(m_lo - mn_lo), a_hi = __expf(m_hi - mn_hi);

        float ps_lo = 0.0f, ps_hi = 0.0f;
#pragma unroll
        for (int nt = 0; nt < 8; nt++) {
            float p0 = __expf(sf[nt][0] - mn_lo);
            float p1 = __expf(sf[nt][1] - mn_lo);
            float p2 = __expf(sf[nt][2] - mn_hi);
            float p3 = __expf(sf[nt][3] - mn_hi);
            ps_lo += p0 + p1;  ps_hi += p2 + p3;
            *(uint2*)&Ps[r * PS_LD + nt * 8 + 2 * c]       = make_uint2(f2tf32(p0), f2tf32(p1));
            *(uint2*)&Ps[(r + 8) * PS_LD + nt * 8 + 2 * c] = make_uint2(f2tf32(p2), f2tf32(p3));
        }
        ps_lo += __shfl_xor_sync(0xffffffffu, ps_lo, 1);
        ps_lo += __shfl_xor_sync(0xffffffffu, ps_lo, 2);
        ps_hi += __shfl_xor_sync(0xffffffffu, ps_hi, 1);
        ps_hi += __shfl_xor_sync(0xffffffffu, ps_hi, 2);
        l_lo = l_lo * a_lo + ps_lo;
        l_hi = l_hi * a_hi + ps_hi;
        m_lo = mn_lo; m_hi = mn_hi;

#pragma unroll
        for (int nt = 0; nt < 8; nt++) {
            of[nt][0] *= a_lo; of[nt][1] *= a_lo;
            of[nt][2] *= a_hi; of[nt][3] *= a_hi;
        }
        __syncwarp();

        // ---- O += P V -------------------------------------------------------
#pragma unroll
        for (int kk = 0; kk < 8; kk++) {
            unsigned pf[4];
            pf[0] = Ps[r * PS_LD + kk * 8 + c];
            pf[1] = Ps[(r + 8) * PS_LD + kk * 8 + c];
            pf[2] = Ps[r * PS_LD + kk * 8 + c + 4];
            pf[3] = Ps[(r + 8) * PS_LD + kk * 8 + c + 4];
#pragma unroll
            for (int nt = 0; nt < 8; nt++) {
                unsigned b0 = Vsb[(kk * 8 + c) * 72 + nt * 8 + r];
                unsigned b1 = Vsb[(kk * 8 + c + 4) * 72 + nt * 8 + r];
                mma8(of[nt], pf, b0, b1);
            }
        }
        buf ^= 1;
    }

    // ---- epilogue: normalize, write AO [B,S,H*D] ----------------------------
    float il_lo = 1.0f / l_lo, il_hi = 1.0f / l_hi;
    size_t rb_lo = ((size_t)b * Sc + qlo) * HDc + h * Dc;
    size_t rb_hi = ((size_t)b * Sc + qhi) * HDc + h * Dc;
#pragma unroll
    for (int nt = 0; nt < 8; nt++) {
        int d = nt * 8 + 2 * c;
        *(float2*)(g_AO + rb_lo + d) = make_float2(of[nt][0] * il_lo, of[nt][1] * il_lo);
        *(float2*)(g_AO + rb_hi + d) = make_float2(of[nt][2] * il_hi, of[nt][3] * il_hi);
    }
}

// ---------------------------------------------------------------------------
extern "C" void kernel_launch(void* const* d_in, const int* in_sizes, int n_in,
                              void* d_out, int out_size)
{
    const float* x  = (const float*)d_in[0];
    const float* Wq = (const float*)d_in[1];
    const float* bq = (const float*)d_in[2];
    const float* Wk = (const float*)d_in[3];
    const float* bk = (const float*)d_in[4];
    const float* Wv = (const float*)d_in[5];
    const float* bv = (const float*)d_in[6];
    const float* Wo = (const float*)d_in[7];
    const float* bo = (const float*)d_in[8];
    float* out = (float*)d_out;

    cudaFuncSetAttribute(flash_tf32_kernel,
                         cudaFuncAttributeMaxDynamicSharedMemorySize, SMEM_BYTES);

    dim3 g1(Hc, Mc / 128, 3);
    gemm_tf32_kernel<0><<<g1, 256>>>(x, Wq, bq, Wk, bk, Wv, bv, nullptr);

    dim3 g2(Sc / 64, Bc * Hc);
    flash_tf32_kernel<<<g2, 128, SMEM_BYTES>>>();

    dim3 g3(Ec / 64, Mc / 128);
    gemm_tf32_kernel<1><<<g3, 256>>>(nullptr, Wo, bo, nullptr, nullptr, nullptr, nullptr, out);
}

// round 5
// speedup vs baseline: 5.9590x; 1.0677x over previous
#include <cuda_runtime.h>

// Problem dims (fixed)
#define Bc  4
#define Sc  2048
#define Ec  1024
#define Hc  16
#define Dc  64
#define HDc (Hc * Dc)      // 1024
#define Mc  (Bc * Sc)      // 8192

// Scratch: Q,K,V in [B,H,S,D] (tf32-rounded fp32); AO in [B,S,H*D]
__device__ float g_Q[Bc * Hc * Sc * Dc];
__device__ float g_K[Bc * Hc * Sc * Dc];
__device__ float g_V[Bc * Hc * Sc * Dc];
__device__ float g_AO[Bc * Sc * HDc];

// ---------------------------------------------------------------------------
// helpers
// ---------------------------------------------------------------------------
__device__ __forceinline__ unsigned f2tf32(float x) {
    unsigned r;
    asm("cvt.rna.tf32.f32 %0, %1;" : "=r"(r) : "f"(x));
    return r;
}
__device__ __forceinline__ float tf32r(float x) { return __uint_as_float(f2tf32(x)); }

__device__ __forceinline__ void mma8(float* d, const unsigned* a, unsigned b0, unsigned b1) {
    asm volatile(
        "mma.sync.aligned.m16n8k8.row.col.f32.tf32.tf32.f32 "
        "{%0,%1,%2,%3}, {%4,%5,%6,%7}, {%8,%9}, {%0,%1,%2,%3};"
        : "+f"(d[0]), "+f"(d[1]), "+f"(d[2]), "+f"(d[3])
        : "r"(a[0]), "r"(a[1]), "r"(a[2]), "r"(a[3]), "r"(b0), "r"(b1));
}

__device__ __forceinline__ void cp16(void* smem, const void* g) {
    unsigned sa = (unsigned)__cvta_generic_to_shared(smem);
    asm volatile("cp.async.cg.shared.global [%0], [%1], 16;" :: "r"(sa), "l"(g));
}
#define CP_COMMIT asm volatile("cp.async.commit_group;")
#define CP_WAIT0  asm volatile("cp.async.wait_group 0;")

// ---------------------------------------------------------------------------
// Kernel 1: FUSED QKV projection (tf32 HMMA).
// Block tile: 128(M) x 192(N=Q|K|V of ONE head) x 32(K). 256 thr = 8 warps
// (4m x 2n), warp tile 32x96 = 2(m16) x 12(n8). The x tile is staged once and
// reused for all three projections -> 3x fewer A-side global reads and 33%
// less smem fragment traffic per MAC vs the round-4 128x64 tiles.
// Bank math: As ld=36 -> frag bank = 4r+c = lane (conflict-free);
//            Bs ld=200 == 8 (mod 32) -> frag bank = 8c+r (conflict-free).
// ---------------------------------------------------------------------------
__global__ __launch_bounds__(256, 1) void qkv_fused_kernel(
    const float* __restrict__ x,
    const float* __restrict__ Wq, const float* __restrict__ bq,
    const float* __restrict__ Wk, const float* __restrict__ bk,
    const float* __restrict__ Wv, const float* __restrict__ bv)
{
    __shared__ unsigned As[128][36];
    __shared__ unsigned Bs[32][200];

    const int tid  = threadIdx.x;
    const int warp = tid >> 5, lane = tid & 31;
    const int wm = warp >> 1, wn = warp & 1;
    const int r = lane >> 2, c = lane & 3;
    const int m0 = blockIdx.x * 128;
    const int h  = blockIdx.y;

    const float* __restrict__ Wmat[3] = {
        Wq + (size_t)h * Ec * Dc,
        Wk + (size_t)h * Ec * Dc,
        Wv + (size_t)h * Ec * Dc };

    float4 pa[4], pb[6];

    // prefetch tile 0
#pragma unroll
    for (int it = 0; it < 4; it++) {
        int i = tid + it * 256; int m = i >> 3; int kq = (i & 7) * 4;
        pa[it] = *(const float4*)(x + (size_t)(m0 + m) * Ec + kq);
    }
#pragma unroll
    for (int it = 0; it < 6; it++) {
        int i = tid + it * 256;                 // 0..1535
        int kb = i / 48, j = i % 48;
        int mat = j >> 4, nq = (j & 15) * 4;
        pb[it] = *(const float4*)(Wmat[mat] + (size_t)kb * Dc + nq);
    }

    float acc[2][12][4];
#pragma unroll
    for (int mt = 0; mt < 2; mt++)
#pragma unroll
        for (int nt = 0; nt < 12; nt++)
#pragma unroll
            for (int j = 0; j < 4; j++) acc[mt][nt][j] = 0.0f;

    for (int k0 = 0; k0 < Ec; k0 += 32) {
        // store staged tile (convert to tf32)
#pragma unroll
        for (int it = 0; it < 4; it++) {
            int i = tid + it * 256; int m = i >> 3; int kq = (i & 7) * 4;
            *(uint4*)&As[m][kq] = make_uint4(f2tf32(pa[it].x), f2tf32(pa[it].y),
                                             f2tf32(pa[it].z), f2tf32(pa[it].w));
        }
#pragma unroll
        for (int it = 0; it < 6; it++) {
            int i = tid + it * 256;
            int kb = i / 48, j = i % 48;
            *(uint4*)&Bs[kb][j * 4] = make_uint4(f2tf32(pb[it].x), f2tf32(pb[it].y),
                                                 f2tf32(pb[it].z), f2tf32(pb[it].w));
        }
        __syncthreads();

        if (k0 + 32 < Ec) {   // prefetch next tile
#pragma unroll
            for (int it = 0; it < 4; it++) {
                int i = tid + it * 256; int m = i >> 3; int kq = (i & 7) * 4;
                pa[it] = *(const float4*)(x + (size_t)(m0 + m) * Ec + k0 + 32 + kq);
            }
#pragma unroll
            for (int it = 0; it < 6; it++) {
                int i = tid + it * 256;
                int kb = i / 48, j = i % 48;
                int mat = j >> 4, nq = (j & 15) * 4;
                pb[it] = *(const float4*)(Wmat[mat] + (size_t)(k0 + 32 + kb) * Dc + nq);
            }
        }

#pragma unroll
        for (int kk = 0; kk < 4; kk++) {
            unsigned af[2][4];
#pragma unroll
            for (int mt = 0; mt < 2; mt++) {
                int R = wm * 32 + mt * 16;
                af[mt][0] = As[R + r][kk * 8 + c];
                af[mt][1] = As[R + r + 8][kk * 8 + c];
                af[mt][2] = As[R + r][kk * 8 + c + 4];
                af[mt][3] = As[R + r + 8][kk * 8 + c + 4];
            }
#pragma unroll
            for (int nt = 0; nt < 12; nt++) {
                int Cn = wn * 96 + nt * 8;
                unsigned b0 = Bs[kk * 8 + c][Cn + r];
                unsigned b1 = Bs[kk * 8 + c + 4][Cn + r];
#pragma unroll
                for (int mt = 0; mt < 2; mt++)
                    mma8(acc[mt][nt], af[mt], b0, b1);
            }
        }
        __syncthreads();
    }

    // epilogue: scatter Q/K/V tiles to [B,H,S,D], tf32-round for flash
    const int bI = m0 >> 11;           // batch index (Sc = 2048)
    const int sBase = m0 & 2047;
#pragma unroll
    for (int nt = 0; nt < 12; nt++) {
        int g   = wn * 96 + nt * 8;    // block-local col 0..191
        int mat = g >> 6;              // 0=Q, 1=K, 2=V (n8 tiles never straddle)
        int d   = (g & 63) + 2 * c;
        float* Out = (mat == 0) ? g_Q : (mat == 1) ? g_K : g_V;
        const float* bias = (mat == 0) ? bq : (mat == 1) ? bk : bv;
        float bb0 = bias[h * Dc + d], bb1 = bias[h * Dc + d + 1];
#pragma unroll
        for (int mt = 0; mt < 2; mt++) {
            int lr = wm * 32 + mt * 16 + r;
            size_t base = ((((size_t)bI * Hc + h) * Sc) + sBase + lr) * Dc + d;
            *(float2*)(Out + base) =
                make_float2(tf32r(acc[mt][nt][0] + bb0), tf32r(acc[mt][nt][1] + bb1));
            *(float2*)(Out + base + 8 * Dc) =
                make_float2(tf32r(acc[mt][nt][2] + bb0), tf32r(acc[mt][nt][3] + bb1));
        }
    }
}

// ---------------------------------------------------------------------------
// Kernel 3: output projection (tf32 HMMA), unchanged from round 4.
// Block 128x64x32, 8 warps (4x2), warp tile 32x32. A = g_AO (device-bound).
// ---------------------------------------------------------------------------
__global__ __launch_bounds__(256) void out_gemm_kernel(
    const float* __restrict__ Wo, const float* __restrict__ bo,
    float* __restrict__ outp)
{
    __shared__ unsigned As[128][36];
    __shared__ unsigned Bs[32][72];

    const float* __restrict__ A = (const float*)g_AO;

    const int tid  = threadIdx.x;
    const int warp = tid >> 5, lane = tid & 31;
    const int wm = warp >> 1, wn = warp & 1;
    const int r = lane >> 2, c = lane & 3;
    const int m0 = blockIdx.y * 128;
    const int ncol0 = blockIdx.x * 64;

    float4 pa[4], pb[2];

#pragma unroll
    for (int it = 0; it < 4; it++) {
        int i = tid + it * 256; int m = i >> 3; int kq = (i & 7) * 4;
        pa[it] = *(const float4*)(A + (size_t)(m0 + m) * HDc + kq);
    }
#pragma unroll
    for (int it = 0; it < 2; it++) {
        int i = tid + it * 256; int kb = i >> 4; int nq = (i & 15) * 4;
        pb[it] = *(const float4*)(Wo + (size_t)kb * Ec + ncol0 + nq);
    }

    float acc[2][4][4];
#pragma unroll
    for (int mt = 0; mt < 2; mt++)
#pragma unroll
        for (int nt = 0; nt < 4; nt++)
#pragma unroll
            for (int j = 0; j < 4; j++) acc[mt][nt][j] = 0.0f;

    for (int k0 = 0; k0 < HDc; k0 += 32) {
#pragma unroll
        for (int it = 0; it < 4; it++) {
            int i = tid + it * 256; int m = i >> 3; int kq = (i & 7) * 4;
            *(uint4*)&As[m][kq] = make_uint4(f2tf32(pa[it].x), f2tf32(pa[it].y),
                                             f2tf32(pa[it].z), f2tf32(pa[it].w));
        }
#pragma unroll
        for (int it = 0; it < 2; it++) {
            int i = tid + it * 256; int kb = i >> 4; int nq = (i & 15) * 4;
            *(uint4*)&Bs[kb][nq] = make_uint4(f2tf32(pb[it].x), f2tf32(pb[it].y),
                                              f2tf32(pb[it].z), f2tf32(pb[it].w));
        }
        __syncthreads();

        if (k0 + 32 < HDc) {
#pragma unroll
            for (int it = 0; it < 4; it++) {
                int i = tid + it * 256; int m = i >> 3; int kq = (i & 7) * 4;
                pa[it] = *(const float4*)(A + (size_t)(m0 + m) * HDc + k0 + 32 + kq);
            }
#pragma unroll
            for (int it = 0; it < 2; it++) {
                int i = tid + it * 256; int kb = i >> 4; int nq = (i & 15) * 4;
                pb[it] = *(const float4*)(Wo + (size_t)(k0 + 32 + kb) * Ec + ncol0 + nq);
            }
        }

#pragma unroll
        for (int kk = 0; kk < 4; kk++) {
            unsigned af[2][4];
#pragma unroll
            for (int mt = 0; mt < 2; mt++) {
                int R = wm * 32 + mt * 16;
                af[mt][0] = As[R + r][kk * 8 + c];
                af[mt][1] = As[R + r + 8][kk * 8 + c];
                af[mt][2] = As[R + r][kk * 8 + c + 4];
                af[mt][3] = As[R + r + 8][kk * 8 + c + 4];
            }
#pragma unroll
            for (int nt = 0; nt < 4; nt++) {
                int Cn = wn * 32 + nt * 8;
                unsigned b0 = Bs[kk * 8 + c][Cn + r];
                unsigned b1 = Bs[kk * 8 + c + 4][Cn + r];
#pragma unroll
                for (int mt = 0; mt < 2; mt++)
                    mma8(acc[mt][nt], af[mt], b0, b1);
            }
        }
        __syncthreads();
    }

#pragma unroll
    for (int mt = 0; mt < 2; mt++) {
        int mrow = m0 + wm * 32 + mt * 16 + r;
#pragma unroll
        for (int nt = 0; nt < 4; nt++) {
            int d = ncol0 + wn * 32 + nt * 8 + 2 * c;
            float bb0 = bo[d], bb1 = bo[d + 1];
            *(float2*)(outp + (size_t)mrow * Ec + d) =
                make_float2(acc[mt][nt][0] + bb0, acc[mt][nt][1] + bb1);
            *(float2*)(outp + (size_t)(mrow + 8) * Ec + d) =
                make_float2(acc[mt][nt][2] + bb0, acc[mt][nt][3] + bb1);
        }
    }
}

// ---------------------------------------------------------------------------
// Kernel 2: flash attention, tf32 tensor cores (unchanged from round 4).
// 128 thr = 4 warps; BQ=64, BKT=64, D=64. cp.async double-buffered K/V.
// Dynamic smem u32 layout:
//   buf0 Ks@0 (64*68)  Vs@4352 (64*72)  | buf1 Ks@8960 Vs@13312
//   Ps@17920 + warp*1088 (16*68)        -> 22272 u32 = 89088 B
// ---------------------------------------------------------------------------
#define PS_LD   68
#define PS_BASE 17920
#define SMEM_BYTES 89088

__device__ __forceinline__ void stage_kv(unsigned* Ksb, unsigned* Vsb,
                                         const float* Kb, const float* Vb,
                                         int k0, int tid)
{
#pragma unroll
    for (int it = 0; it < 8; it++) {
        int i = tid + it * 128;
        int row = i >> 4;
        int cq = (i & 15) * 4;
        cp16(&Ksb[row * 68 + cq], Kb + (size_t)(k0 + row) * Dc + cq);
        cp16(&Vsb[row * 72 + cq], Vb + (size_t)(k0 + row) * Dc + cq);
    }
}

__global__ __launch_bounds__(128) void flash_tf32_kernel()
{
    extern __shared__ __align__(16) unsigned sm[];

    const int bh = blockIdx.y;
    const int b  = bh >> 4, h = bh & 15;
    const int q0 = blockIdx.x * 64;

    const float* __restrict__ Qb = g_Q + (size_t)bh * Sc * Dc;
    const float* __restrict__ Kb = g_K + (size_t)bh * Sc * Dc;
    const float* __restrict__ Vb = g_V + (size_t)bh * Sc * Dc;

    const int tid  = threadIdx.x;
    const int warp = tid >> 5, lane = tid & 31;
    const int r = lane >> 2, c = lane & 3;

    // stage Q through buf0's Ks region, extract A-fragments
#pragma unroll
    for (int it = 0; it < 8; it++) {
        int i = tid + it * 128;
        int row = i >> 4, cq = (i & 15) * 4;
        *(uint4*)&sm[row * 68 + cq] = *(const uint4*)(Qb + (size_t)(q0 + row) * Dc + cq);
    }
    __syncthreads();
    unsigned qf[8][4];
    {
        int R = warp * 16;
#pragma unroll
        for (int kk = 0; kk < 8; kk++) {
            qf[kk][0] = sm[(R + r) * 68 + kk * 8 + c];
            qf[kk][1] = sm[(R + r + 8) * 68 + kk * 8 + c];
            qf[kk][2] = sm[(R + r) * 68 + kk * 8 + c + 4];
            qf[kk][3] = sm[(R + r + 8) * 68 + kk * 8 + c + 4];
        }
    }
    __syncthreads();

    unsigned* Ps = sm + PS_BASE + warp * (16 * PS_LD);

    const int nkt = blockIdx.x + 1;
    stage_kv(sm, sm + 4352, Kb, Vb, 0, tid);
    CP_COMMIT;

    float of[8][4];
#pragma unroll
    for (int nt = 0; nt < 8; nt++)
#pragma unroll
        for (int j = 0; j < 4; j++) of[nt][j] = 0.0f;
    float m_lo = -1e30f, m_hi = -1e30f, l_lo = 0.0f, l_hi = 0.0f;

    const int qlo = q0 + warp * 16 + r;
    const int qhi = qlo + 8;

    int buf = 0;
    for (int kt = 0; kt < nkt; kt++) {
        CP_WAIT0;
        __syncthreads();
        if (kt + 1 < nkt) {
            int nb = buf ^ 1;
            stage_kv(sm + nb * 8960, sm + nb * 8960 + 4352, Kb, Vb, (kt + 1) * 64, tid);
            CP_COMMIT;
        }
        unsigned* Ksb = sm + buf * 8960;
        unsigned* Vsb = Ksb + 4352;

        // S = Q K^T
        float sf[8][4];
#pragma unroll
        for (int nt = 0; nt < 8; nt++) {
            sf[nt][0] = sf[nt][1] = sf[nt][2] = sf[nt][3] = 0.0f;
#pragma unroll
            for (int kk = 0; kk < 8; kk++) {
                unsigned b0 = Ksb[(nt * 8 + r) * 68 + kk * 8 + c];
                unsigned b1 = Ksb[(nt * 8 + r) * 68 + kk * 8 + c + 4];
                mma8(sf[nt], qf[kk], b0, b1);
            }
        }

        // scale + causal mask + online softmax
        const int kbase = kt * 64;
        float mx_lo = -1e30f, mx_hi = -1e30f;
#pragma unroll
        for (int nt = 0; nt < 8; nt++) {
            int kg0 = kbase + nt * 8 + 2 * c;
            int kg1 = kg0 + 1;
            float s0 = sf[nt][0] * 0.125f; if (kg0 > qlo) s0 = -1e30f;
            float s1 = sf[nt][1] * 0.125f; if (kg1 > qlo) s1 = -1e30f;
            float s2 = sf[nt][2] * 0.125f; if (kg0 > qhi) s2 = -1e30f;
            float s3 = sf[nt][3] * 0.125f; if (kg1 > qhi) s3 = -1e30f;
            sf[nt][0] = s0; sf[nt][1] = s1; sf[nt][2] = s2; sf[nt][3] = s3;
            mx_lo = fmaxf(mx_lo, fmaxf(s0, s1));
            mx_hi = fmaxf(mx_hi, fmaxf(s2, s3));
        }
        mx_lo = fmaxf(mx_lo, __shfl_xor_sync(0xffffffffu, mx_lo, 1));
        mx_lo = fmaxf(mx_lo, __shfl_xor_sync(0xffffffffu, mx_lo, 2));
        mx_hi = fmaxf(mx_hi, __shfl_xor_sync(0xffffffffu, mx_hi, 1));
        mx_hi = fmaxf(mx_hi, __shfl_xor_sync(0xffffffffu, mx_hi, 2));

        float mn_lo = fmaxf(m_lo, mx_lo), mn_hi = fmaxf(m_hi, mx_hi);
        float a_lo = __expf(m_lo - mn_lo), a_hi = __expf(m_hi - mn_hi);

        float ps_lo = 0.0f, ps_hi = 0.0f;
#pragma unroll
        for (int nt = 0; nt < 8; nt++) {
            float p0 = __expf(sf[nt][0] - mn_lo);
            float p1 = __expf(sf[nt][1] - mn_lo);
            float p2 = __expf(sf[nt][2] - mn_hi);
            float p3 = __expf(sf[nt][3] - mn_hi);
            ps_lo += p0 + p1;  ps_hi += p2 + p3;
            *(uint2*)&Ps[r * PS_LD + nt * 8 + 2 * c]       = make_uint2(f2tf32(p0), f2tf32(p1));
            *(uint2*)&Ps[(r + 8) * PS_LD + nt * 8 + 2 * c] = make_uint2(f2tf32(p2), f2tf32(p3));
        }
        ps_lo += __shfl_xor_sync(0xffffffffu, ps_lo, 1);
        ps_lo += __shfl_xor_sync(0xffffffffu, ps_lo, 2);
        ps_hi += __shfl_xor_sync(0xffffffffu, ps_hi, 1);
        ps_hi += __shfl_xor_sync(0xffffffffu, ps_hi, 2);
        l_lo = l_lo * a_lo + ps_lo;
        l_hi = l_hi * a_hi + ps_hi;
        m_lo = mn_lo; m_hi = mn_hi;

#pragma unroll
        for (int nt = 0; nt < 8; nt++) {
            of[nt][0] *= a_lo; of[nt][1] *= a_lo;
            of[nt][2] *= a_hi; of[nt][3] *= a_hi;
        }
        __syncwarp();

        // O += P V
#pragma unroll
        for (int kk = 0; kk < 8; kk++) {
            unsigned pf[4];
            pf[0] = Ps[r * PS_LD + kk * 8 + c];
            pf[1] = Ps[(r + 8) * PS_LD + kk * 8 + c];
            pf[2] = Ps[r * PS_LD + kk * 8 + c + 4];
            pf[3] = Ps[(r + 8) * PS_LD + kk * 8 + c + 4];
#pragma unroll
            for (int nt = 0; nt < 8; nt++) {
                unsigned b0 = Vsb[(kk * 8 + c) * 72 + nt * 8 + r];
                unsigned b1 = Vsb[(kk * 8 + c + 4) * 72 + nt * 8 + r];
                mma8(of[nt], pf, b0, b1);
            }
        }
        buf ^= 1;
    }

    // epilogue: normalize, write AO [B,S,H*D]
    float il_lo = 1.0f / l_lo, il_hi = 1.0f / l_hi;
    size_t rb_lo = ((size_t)b * Sc + qlo) * HDc + h * Dc;
    size_t rb_hi = ((size_t)b * Sc + qhi) * HDc + h * Dc;
#pragma unroll
    for (int nt = 0; nt < 8; nt++) {
        int d = nt * 8 + 2 * c;
        *(float2*)(g_AO + rb_lo + d) = make_float2(of[nt][0] * il_lo, of[nt][1] * il_lo);
        *(float2*)(g_AO + rb_hi + d) = make_float2(of[nt][2] * il_hi, of[nt][3] * il_hi);
    }
}

// ---------------------------------------------------------------------------
extern "C" void kernel_launch(void* const* d_in, const int* in_sizes, int n_in,
                              void* d_out, int out_size)
{
    const float* x  = (const float*)d_in[0];
    const float* Wq = (const float*)d_in[1];
    const float* bq = (const float*)d_in[2];
    const float* Wk = (const float*)d_in[3];
    const float* bk = (const float*)d_in[4];
    const float* Wv = (const float*)d_in[5];
    const float* bv = (const float*)d_in[6];
    const float* Wo = (const float*)d_in[7];
    const float* bo = (const float*)d_in[8];
    float* out = (float*)d_out;

    cudaFuncSetAttribute(flash_tf32_kernel,
                         cudaFuncAttributeMaxDynamicSharedMemorySize, SMEM_BYTES);

    dim3 g1(Mc / 128, Hc);
    qkv_fused_kernel<<<g1, 256>>>(x, Wq, bq, Wk, bk, Wv, bv);

    dim3 g2(Sc / 64, Bc * Hc);
    flash_tf32_kernel<<<g2, 128, SMEM_BYTES>>>();

    dim3 g3(Ec / 64, Mc / 128);
    out_gemm_kernel<<<g3, 256>>>(Wo, bo, out);
}

// round 6
// speedup vs baseline: 6.3647x; 1.0681x over previous
#include <cuda_runtime.h>

// Problem dims (fixed)
#define Bc  4
#define Sc  2048
#define Ec  1024
#define Hc  16
#define Dc  64
#define HDc (Hc * Dc)      // 1024
#define Mc  (Bc * Sc)      // 8192

// Scratch
__device__ float g_Q[Bc * Hc * Sc * Dc];
__device__ float g_K[Bc * Hc * Sc * Dc];
__device__ float g_V[Bc * Hc * Sc * Dc];
__device__ float g_AO[Bc * Sc * HDc];        // tf32-rounded by flash epilogue
// tf32-pre-rounded copies (prepass)
__device__ float g_xr [Mc * Ec];
__device__ float g_Wqr[Hc * Ec * Dc];
__device__ float g_Wkr[Hc * Ec * Dc];
__device__ float g_Wvr[Hc * Ec * Dc];
__device__ float g_Wor[HDc * Ec];

// ---------------------------------------------------------------------------
// helpers
// ---------------------------------------------------------------------------
__device__ __forceinline__ unsigned f2tf32(float x) {
    unsigned r;
    asm("cvt.rna.tf32.f32 %0, %1;" : "=r"(r) : "f"(x));
    return r;
}
__device__ __forceinline__ float tf32r(float x) { return __uint_as_float(f2tf32(x)); }

__device__ __forceinline__ void mma8(float* d, const unsigned* a, unsigned b0, unsigned b1) {
    asm volatile(
        "mma.sync.aligned.m16n8k8.row.col.f32.tf32.tf32.f32 "
        "{%0,%1,%2,%3}, {%4,%5,%6,%7}, {%8,%9}, {%0,%1,%2,%3};"
        : "+f"(d[0]), "+f"(d[1]), "+f"(d[2]), "+f"(d[3])
        : "r"(a[0]), "r"(a[1]), "r"(a[2]), "r"(a[3]), "r"(b0), "r"(b1));
}

__device__ __forceinline__ void cp16(void* smem, const void* g) {
    unsigned sa = (unsigned)__cvta_generic_to_shared(smem);
    asm volatile("cp.async.cg.shared.global [%0], [%1], 16;" :: "r"(sa), "l"(g));
}
#define CP_COMMIT asm volatile("cp.async.commit_group;")
#define CP_WAIT0  asm volatile("cp.async.wait_group 0;")

// ---------------------------------------------------------------------------
// Kernel 0: prepass — RNA-round inputs to tf32 once (removes CVT from all
// GEMM hot loops; numerically identical to rounding per-tile).
// blockIdx.y selects array. Grid-stride float4.
// ---------------------------------------------------------------------------
__global__ __launch_bounds__(256) void prepass_kernel(
    const float* __restrict__ x,
    const float* __restrict__ Wq, const float* __restrict__ Wk,
    const float* __restrict__ Wv, const float* __restrict__ Wo)
{
    const float4* src; float4* dst; int n4;
    switch (blockIdx.y) {
        case 0: src = (const float4*)x;  dst = (float4*)g_xr;  n4 = Mc * Ec / 4;      break;
        case 1: src = (const float4*)Wq; dst = (float4*)g_Wqr; n4 = Hc * Ec * Dc / 4; break;
        case 2: src = (const float4*)Wk; dst = (float4*)g_Wkr; n4 = Hc * Ec * Dc / 4; break;
        case 3: src = (const float4*)Wv; dst = (float4*)g_Wvr; n4 = Hc * Ec * Dc / 4; break;
        default:src = (const float4*)Wo; dst = (float4*)g_Wor; n4 = HDc * Ec / 4;     break;
    }
    for (int i = blockIdx.x * blockDim.x + threadIdx.x; i < n4;
         i += gridDim.x * blockDim.x) {
        float4 v = src[i];
        dst[i] = make_float4(tf32r(v.x), tf32r(v.y), tf32r(v.z), tf32r(v.w));
    }
}

// ---------------------------------------------------------------------------
// Kernel 1: FUSED QKV projection. Block 128(M) x 192(N = Q|K|V of one head)
// x 32(K). 8 warps (4m x 2n), warp tile 32x96. cp.async double-buffered smem,
// no conversions, no staging registers.
// smem (u32): As0@0 As1@4608 (128x36 each) | Bs0@9216 Bs1@15616 (32x200 each)
// Bank math: As ld=36 -> frag bank = 4r+c = lane; Bs ld=200==8(mod32) -> 8c+r.
// ---------------------------------------------------------------------------
#define QKV_AS(buf) ((buf) * 4608)
#define QKV_BS(buf) (9216 + (buf) * 6400)
#define QKV_SMEM_BYTES (22016 * 4)

__global__ __launch_bounds__(256, 1) void qkv_fused_kernel(
    const float* __restrict__ bq, const float* __restrict__ bk,
    const float* __restrict__ bv)
{
    extern __shared__ __align__(16) unsigned smq[];

    const int tid  = threadIdx.x;
    const int warp = tid >> 5, lane = tid & 31;
    const int wm = warp >> 1, wn = warp & 1;
    const int r = lane >> 2, c = lane & 3;
    const int m0 = blockIdx.x * 128;
    const int h  = blockIdx.y;

    const float* __restrict__ Wr[3] = {
        g_Wqr + (size_t)h * Ec * Dc,
        g_Wkr + (size_t)h * Ec * Dc,
        g_Wvr + (size_t)h * Ec * Dc };
    const float* __restrict__ xr = g_xr;

    // stage tile 0 into buf 0
#pragma unroll
    for (int it = 0; it < 4; it++) {
        int i = tid + it * 256; int m = i >> 3; int kq = (i & 7) * 4;
        cp16(&smq[QKV_AS(0) + m * 36 + kq], xr + (size_t)(m0 + m) * Ec + kq);
    }
#pragma unroll
    for (int it = 0; it < 6; it++) {
        int i = tid + it * 256; int kb = i / 48, j = i % 48;
        cp16(&smq[QKV_BS(0) + kb * 200 + j * 4],
             Wr[j >> 4] + (size_t)kb * Dc + (j & 15) * 4);
    }
    CP_COMMIT;

    float acc[2][12][4];
#pragma unroll
    for (int mt = 0; mt < 2; mt++)
#pragma unroll
        for (int nt = 0; nt < 12; nt++)
#pragma unroll
            for (int j = 0; j < 4; j++) acc[mt][nt][j] = 0.0f;

    int buf = 0;
    for (int k0 = 0; k0 < Ec; k0 += 32, buf ^= 1) {
        CP_WAIT0;
        __syncthreads();

        if (k0 + 32 < Ec) {   // stage next tile into buf^1 (overlaps compute)
            int nb = buf ^ 1;
#pragma unroll
            for (int it = 0; it < 4; it++) {
                int i = tid + it * 256; int m = i >> 3; int kq = (i & 7) * 4;
                cp16(&smq[QKV_AS(nb) + m * 36 + kq],
                     xr + (size_t)(m0 + m) * Ec + k0 + 32 + kq);
            }
#pragma unroll
            for (int it = 0; it < 6; it++) {
                int i = tid + it * 256; int kb = i / 48, j = i % 48;
                cp16(&smq[QKV_BS(nb) + kb * 200 + j * 4],
                     Wr[j >> 4] + (size_t)(k0 + 32 + kb) * Dc + (j & 15) * 4);
            }
            CP_COMMIT;
        }

        const unsigned* As = smq + QKV_AS(buf);
        const unsigned* Bs = smq + QKV_BS(buf);
#pragma unroll
        for (int kk = 0; kk < 4; kk++) {
            unsigned af[2][4];
#pragma unroll
            for (int mt = 0; mt < 2; mt++) {
                int R = wm * 32 + mt * 16;
                af[mt][0] = As[(R + r) * 36 + kk * 8 + c];
                af[mt][1] = As[(R + r + 8) * 36 + kk * 8 + c];
                af[mt][2] = As[(R + r) * 36 + kk * 8 + c + 4];
                af[mt][3] = As[(R + r + 8) * 36 + kk * 8 + c + 4];
            }
#pragma unroll
            for (int nt = 0; nt < 12; nt++) {
                int Cn = wn * 96 + nt * 8;
                unsigned b0 = Bs[(kk * 8 + c) * 200 + Cn + r];
                unsigned b1 = Bs[(kk * 8 + c + 4) * 200 + Cn + r];
#pragma unroll
                for (int mt = 0; mt < 2; mt++)
                    mma8(acc[mt][nt], af[mt], b0, b1);
            }
        }
    }

    // epilogue: scatter Q/K/V to [B,H,S,D], tf32-round for flash
    const int bI = m0 >> 11;
    const int sBase = m0 & 2047;
#pragma unroll
    for (int nt = 0; nt < 12; nt++) {
        int g   = wn * 96 + nt * 8;
        int mat = g >> 6;
        int d   = (g & 63) + 2 * c;
        float* Out = (mat == 0) ? g_Q : (mat == 1) ? g_K : g_V;
        const float* bias = (mat == 0) ? bq : (mat == 1) ? bk : bv;
        float bb0 = bias[h * Dc + d], bb1 = bias[h * Dc + d + 1];
#pragma unroll
        for (int mt = 0; mt < 2; mt++) {
            int lr = wm * 32 + mt * 16 + r;
            size_t base = ((((size_t)bI * Hc + h) * Sc) + sBase + lr) * Dc + d;
            *(float2*)(Out + base) =
                make_float2(tf32r(acc[mt][nt][0] + bb0), tf32r(acc[mt][nt][1] + bb1));
            *(float2*)(Out + base + 8 * Dc) =
                make_float2(tf32r(acc[mt][nt][2] + bb0), tf32r(acc[mt][nt][3] + bb1));
        }
    }
}

// ---------------------------------------------------------------------------
// Kernel 3: output projection. Block 128(M) x 128(N) x 32(K), 8 warps (4x2),
// warp tile 32x64. cp.async double-buffered; A = g_AO (pre-rounded by flash),
// B = g_Wor (pre-rounded). fp32 epilogue.
// smem (u32): As0@0 As1@4608 | Bs0@9216 Bs1@13568 (32x136 each) = 17920 u32
// Bs ld=136==8(mod32) -> frag bank = 8c+r (conflict-free).
// ---------------------------------------------------------------------------
#define O_AS(buf) ((buf) * 4608)
#define O_BS(buf) (9216 + (buf) * 4352)
#define O_SMEM_BYTES (17920 * 4)

__global__ __launch_bounds__(256, 1) void out_gemm_kernel(
    const float* __restrict__ bo, float* __restrict__ outp)
{
    extern __shared__ __align__(16) unsigned smo[];

    const float* __restrict__ A = (const float*)g_AO;
    const float* __restrict__ B = (const float*)g_Wor;

    const int tid  = threadIdx.x;
    const int warp = tid >> 5, lane = tid & 31;
    const int wm = warp >> 1, wn = warp & 1;
    const int r = lane >> 2, c = lane & 3;
    const int m0 = blockIdx.y * 128;
    const int ncol0 = blockIdx.x * 128;

    // stage tile 0
#pragma unroll
    for (int it = 0; it < 4; it++) {
        int i = tid + it * 256; int m = i >> 3; int kq = (i & 7) * 4;
        cp16(&smo[O_AS(0) + m * 36 + kq], A + (size_t)(m0 + m) * HDc + kq);
    }
#pragma unroll
    for (int it = 0; it < 4; it++) {
        int i = tid + it * 256; int kb = i >> 5; int nq = (i & 31) * 4;
        cp16(&smo[O_BS(0) + kb * 136 + nq], B + (size_t)kb * Ec + ncol0 + nq);
    }
    CP_COMMIT;

    float acc[2][8][4];
#pragma unroll
    for (int mt = 0; mt < 2; mt++)
#pragma unroll
        for (int nt = 0; nt < 8; nt++)
#pragma unroll
            for (int j = 0; j < 4; j++) acc[mt][nt][j] = 0.0f;

    int buf = 0;
    for (int k0 = 0; k0 < HDc; k0 += 32, buf ^= 1) {
        CP_WAIT0;
        __syncthreads();

        if (k0 + 32 < HDc) {
            int nb = buf ^ 1;
#pragma unroll
            for (int it = 0; it < 4; it++) {
                int i = tid + it * 256; int m = i >> 3; int kq = (i & 7) * 4;
                cp16(&smo[O_AS(nb) + m * 36 + kq],
                     A + (size_t)(m0 + m) * HDc + k0 + 32 + kq);
            }
#pragma unroll
            for (int it = 0; it < 4; it++) {
                int i = tid + it * 256; int kb = i >> 5; int nq = (i & 31) * 4;
                cp16(&smo[O_BS(nb) + kb * 136 + nq],
                     B + (size_t)(k0 + 32 + kb) * Ec + ncol0 + nq);
            }
            CP_COMMIT;
        }

        const unsigned* As = smo + O_AS(buf);
        const unsigned* Bs = smo + O_BS(buf);
#pragma unroll
        for (int kk = 0; kk < 4; kk++) {
            unsigned af[2][4];
#pragma unroll
            for (int mt = 0; mt < 2; mt++) {
                int R = wm * 32 + mt * 16;
                af[mt][0] = As[(R + r) * 36 + kk * 8 + c];
                af[mt][1] = As[(R + r + 8) * 36 + kk * 8 + c];
                af[mt][2] = As[(R + r) * 36 + kk * 8 + c + 4];
                af[mt][3] = As[(R + r + 8) * 36 + kk * 8 + c + 4];
            }
#pragma unroll
            for (int nt = 0; nt < 8; nt++) {
                int Cn = wn * 64 + nt * 8;
                unsigned b0 = Bs[(kk * 8 + c) * 136 + Cn + r];
                unsigned b1 = Bs[(kk * 8 + c + 4) * 136 + Cn + r];
#pragma unroll
                for (int mt = 0; mt < 2; mt++)
                    mma8(acc[mt][nt], af[mt], b0, b1);
            }
        }
    }

#pragma unroll
    for (int mt = 0; mt < 2; mt++) {
        int mrow = m0 + wm * 32 + mt * 16 + r;
#pragma unroll
        for (int nt = 0; nt < 8; nt++) {
            int d = ncol0 + wn * 64 + nt * 8 + 2 * c;
            float bb0 = bo[d], bb1 = bo[d + 1];
            *(float2*)(outp + (size_t)mrow * Ec + d) =
                make_float2(acc[mt][nt][0] + bb0, acc[mt][nt][1] + bb1);
            *(float2*)(outp + (size_t)(mrow + 8) * Ec + d) =
                make_float2(acc[mt][nt][2] + bb0, acc[mt][nt][3] + bb1);
        }
    }
}

// ---------------------------------------------------------------------------
// Kernel 2: flash attention (tf32 HMMA) — unchanged from round 5 except the
// epilogue writes tf32-rounded AO (feeds the pre-rounded out-proj path).
// ---------------------------------------------------------------------------
#define PS_LD   68
#define PS_BASE 17920
#define SMEM_BYTES 89088

__device__ __forceinline__ void stage_kv(unsigned* Ksb, unsigned* Vsb,
                                         const float* Kb, const float* Vb,
                                         int k0, int tid)
{
#pragma unroll
    for (int it = 0; it < 8; it++) {
        int i = tid + it * 128;
        int row = i >> 4;
        int cq = (i & 15) * 4;
        cp16(&Ksb[row * 68 + cq], Kb + (size_t)(k0 + row) * Dc + cq);
        cp16(&Vsb[row * 72 + cq], Vb + (size_t)(k0 + row) * Dc + cq);
    }
}

__global__ __launch_bounds__(128) void flash_tf32_kernel()
{
    extern __shared__ __align__(16) unsigned sm[];

    const int bh = blockIdx.y;
    const int b  = bh >> 4, h = bh & 15;
    const int q0 = blockIdx.x * 64;

    const float* __restrict__ Qb = g_Q + (size_t)bh * Sc * Dc;
    const float* __restrict__ Kb = g_K + (size_t)bh * Sc * Dc;
    const float* __restrict__ Vb = g_V + (size_t)bh * Sc * Dc;

    const int tid  = threadIdx.x;
    const int warp = tid >> 5, lane = tid & 31;
    const int r = lane >> 2, c = lane & 3;

#pragma unroll
    for (int it = 0; it < 8; it++) {
        int i = tid + it * 128;
        int row = i >> 4, cq = (i & 15) * 4;
        *(uint4*)&sm[row * 68 + cq] = *(const uint4*)(Qb + (size_t)(q0 + row) * Dc + cq);
    }
    __syncthreads();
    unsigned qf[8][4];
    {
        int R = warp * 16;
#pragma unroll
        for (int kk = 0; kk < 8; kk++) {
            qf[kk][0] = sm[(R + r) * 68 + kk * 8 + c];
            qf[kk][1] = sm[(R + r + 8) * 68 + kk * 8 + c];
            qf[kk][2] = sm[(R + r) * 68 + kk * 8 + c + 4];
            qf[kk][3] = sm[(R + r + 8) * 68 + kk * 8 + c + 4];
        }
    }
    __syncthreads();

    unsigned* Ps = sm + PS_BASE + warp * (16 * PS_LD);

    const int nkt = blockIdx.x + 1;
    stage_kv(sm, sm + 4352, Kb, Vb, 0, tid);
    CP_COMMIT;

    float of[8][4];
#pragma unroll
    for (int nt = 0; nt < 8; nt++)
#pragma unroll
        for (int j = 0; j < 4; j++) of[nt][j] = 0.0f;
    float m_lo = -1e30f, m_hi = -1e30f, l_lo = 0.0f, l_hi = 0.0f;

    const int qlo = q0 + warp * 16 + r;
    const int qhi = qlo + 8;

    int buf = 0;
    for (int kt = 0; kt < nkt; kt++) {
        CP_WAIT0;
        __syncthreads();
        if (kt + 1 < nkt) {
            int nb = buf ^ 1;
            stage_kv(sm + nb * 8960, sm + nb * 8960 + 4352, Kb, Vb, (kt + 1) * 64, tid);
            CP_COMMIT;
        }
        unsigned* Ksb = sm + buf * 8960;
        unsigned* Vsb = Ksb + 4352;

        float sf[8][4];
#pragma unroll
        for (int nt = 0; nt < 8; nt++) {
            sf[nt][0] = sf[nt][1] = sf[nt][2] = sf[nt][3] = 0.0f;
#pragma unroll
            for (int kk = 0; kk < 8; kk++) {
                unsigned b0 = Ksb[(nt * 8 + r) * 68 + kk * 8 + c];
                unsigned b1 = Ksb[(nt * 8 + r) * 68 + kk * 8 + c + 4];
                mma8(sf[nt], qf[kk], b0, b1);
            }
        }

        const int kbase = kt * 64;
        float mx_lo = -1e30f, mx_hi = -1e30f;
#pragma unroll
        for (int nt = 0; nt < 8; nt++) {
            int kg0 = kbase + nt * 8 + 2 * c;
            int kg1 = kg0 + 1;
            float s0 = sf[nt][0] * 0.125f; if (kg0 > qlo) s0 = -1e30f;
            float s1 = sf[nt][1] * 0.125f; if (kg1 > qlo) s1 = -1e30f;
            float s2 = sf[nt][2] * 0.125f; if (kg0 > qhi) s2 = -1e30f;
            float s3 = sf[nt][3] * 0.125f; if (kg1 > qhi) s3 = -1e30f;
            sf[nt][0] = s0; sf[nt][1] = s1; sf[nt][2] = s2; sf[nt][3] = s3;
            mx_lo = fmaxf(mx_lo, fmaxf(s0, s1));
            mx_hi = fmaxf(mx_hi, fmaxf(s2, s3));
        }
        mx_lo = fmaxf(mx_lo, __shfl_xor_sync(0xffffffffu, mx_lo, 1));
        mx_lo = fmaxf(mx_lo, __shfl_xor_sync(0xffffffffu, mx_lo, 2));
        mx_hi = fmaxf(mx_hi, __shfl_xor_sync(0xffffffffu, mx_hi, 1));
        mx_hi = fmaxf(mx_hi, __shfl_xor_sync(0xffffffffu, mx_hi, 2));

        float mn_lo = fmaxf(m_lo, mx_lo), mn_hi = fmaxf(m_hi, mx_hi);
        float a_lo = __expf(m_lo - mn_lo), a_hi = __expf(m_hi - mn_hi);

        float ps_lo = 0.0f, ps_hi = 0.0f;
#pragma unroll
        for (int nt = 0; nt < 8; nt++) {
            float p0 = __expf(sf[nt][0] - mn_lo);
            float p1 = __expf(sf[nt][1] - mn_lo);
            float p2 = __expf(sf[nt][2] - mn_hi);
            float p3 = __expf(sf[nt][3] - mn_hi);
            ps_lo += p0 + p1;  ps_hi += p2 + p3;
            *(uint2*)&Ps[r * PS_LD + nt * 8 + 2 * c]       = make_uint2(f2tf32(p0), f2tf32(p1));
            *(uint2*)&Ps[(r + 8) * PS_LD + nt * 8 + 2 * c] = make_uint2(f2tf32(p2), f2tf32(p3));
        }
        ps_lo += __shfl_xor_sync(0xffffffffu, ps_lo, 1);
        ps_lo += __shfl_xor_sync(0xffffffffu, ps_lo, 2);
        ps_hi += __shfl_xor_sync(0xffffffffu, ps_hi, 1);
        ps_hi += __shfl_xor_sync(0xffffffffu, ps_hi, 2);
        l_lo = l_lo * a_lo + ps_lo;
        l_hi = l_hi * a_hi + ps_hi;
        m_lo = mn_lo; m_hi = mn_hi;

#pragma unroll
        for (int nt = 0; nt < 8; nt++) {
            of[nt][0] *= a_lo; of[nt][1] *= a_lo;
            of[nt][2] *= a_hi; of[nt][3] *= a_hi;
        }
        __syncwarp();

#pragma unroll
        for (int kk = 0; kk < 8; kk++) {
            unsigned pf[4];
            pf[0] = Ps[r * PS_LD + kk * 8 + c];
            pf[1] = Ps[(r + 8) * PS_LD + kk * 8 + c];
            pf[2] = Ps[r * PS_LD + kk * 8 + c + 4];
            pf[3] = Ps[(r + 8) * PS_LD + kk * 8 + c + 4];
#pragma unroll
            for (int nt = 0; nt < 8; nt++) {
                unsigned b0 = Vsb[(kk * 8 + c) * 72 + nt * 8 + r];
                unsigned b1 = Vsb[(kk * 8 + c + 4) * 72 + nt * 8 + r];
                mma8(of[nt], pf, b0, b1);
            }
        }
        buf ^= 1;
    }

    // epilogue: normalize, tf32-round, write AO [B,S,H*D]
    float il_lo = 1.0f / l_lo, il_hi = 1.0f / l_hi;
    size_t rb_lo = ((size_t)b * Sc + qlo) * HDc + h * Dc;
    size_t rb_hi = ((size_t)b * Sc + qhi) * HDc + h * Dc;
#pragma unroll
    for (int nt = 0; nt < 8; nt++) {
        int d = nt * 8 + 2 * c;
        *(float2*)(g_AO + rb_lo + d) =
            make_float2(tf32r(of[nt][0] * il_lo), tf32r(of[nt][1] * il_lo));
        *(float2*)(g_AO + rb_hi + d) =
            make_float2(tf32r(of[nt][2] * il_hi), tf32r(of[nt][3] * il_hi));
    }
}

// ---------------------------------------------------------------------------
extern "C" void kernel_launch(void* const* d_in, const int* in_sizes, int n_in,
                              void* d_out, int out_size)
{
    const float* x  = (const float*)d_in[0];
    const float* Wq = (const float*)d_in[1];
    const float* bq = (const float*)d_in[2];
    const float* Wk = (const float*)d_in[3];
    const float* bk = (const float*)d_in[4];
    const float* Wv = (const float*)d_in[5];
    const float* bv = (const float*)d_in[6];
    const float* Wo = (const float*)d_in[7];
    const float* bo = (const float*)d_in[8];
    float* out = (float*)d_out;

    cudaFuncSetAttribute(qkv_fused_kernel,
                         cudaFuncAttributeMaxDynamicSharedMemorySize, QKV_SMEM_BYTES);
    cudaFuncSetAttribute(flash_tf32_kernel,
                         cudaFuncAttributeMaxDynamicSharedMemorySize, SMEM_BYTES);
    cudaFuncSetAttribute(out_gemm_kernel,
                         cudaFuncAttributeMaxDynamicSharedMemorySize, O_SMEM_BYTES);

    dim3 g0(448, 5);
    prepass_kernel<<<g0, 256>>>(x, Wq, Wk, Wv, Wo);

    dim3 g1(Mc / 128, Hc);
    qkv_fused_kernel<<<g1, 256, QKV_SMEM_BYTES>>>(bq, bk, bv);

    dim3 g2(Sc / 64, Bc * Hc);
    flash_tf32_kernel<<<g2, 128, SMEM_BYTES>>>();

    dim3 g3(Ec / 128, Mc / 128);
    out_gemm_kernel<<<g3, 256, O_SMEM_BYTES>>>(bo, out);
}